// round 8
// baseline (speedup 1.0000x reference)
#include <cuda_runtime.h>
#include <math.h>

#define D_INNER 8192
#define D_MODEL 4096
#define DT_RANK 8
#define D_STATE 16
#define XP_DIM  (DT_RANK + 2 * D_STATE)   // 40
#define KT_XP   1024

// Scratch
__device__ float g_x_conv[D_INNER];
__device__ float g_z_silu[D_INNER];
__device__ float g_xp[XP_DIM];
__device__ float g_y[D_INNER];

// ---------------------------------------------------------------------------
// Kernel 1: xz = W_in @ x (16384 x 4096) + fused conv/silu epilogue.
// 128-thread blocks, 16 blocks/SM (32-reg budget), warp-per-row, no smem.
// grid = 4096 (1.73 waves, full fill).
// ---------------------------------------------------------------------------
__global__ __launch_bounds__(128, 16) void k_win(
    const float* __restrict__ W_in,
    const float* __restrict__ x,
    const float* __restrict__ conv_buffer,
    const float* __restrict__ conv_w,
    const float* __restrict__ conv_b)
{
    const int tid  = threadIdx.x;
    const int lane = tid & 31;
    const int warp = tid >> 5;
    if (blockIdx.x == 0 && tid < XP_DIM) g_xp[tid] = 0.0f;

    const int row = blockIdx.x * 4 + warp;
    const float4* w4 = (const float4*)(W_in + (size_t)row * D_MODEL);
    const float4* x4 = (const float4*)x;

    float acc0 = 0.0f, acc1 = 0.0f;
    #pragma unroll
    for (int i = lane; i < D_MODEL / 4; i += 64) {
        float4 wa = __ldcs(&w4[i]);
        float4 wb = __ldcs(&w4[i + 32]);
        float4 va = x4[i];
        float4 vb = x4[i + 32];
        acc0 = fmaf(wa.x, va.x, acc0); acc0 = fmaf(wa.y, va.y, acc0);
        acc0 = fmaf(wa.z, va.z, acc0); acc0 = fmaf(wa.w, va.w, acc0);
        acc1 = fmaf(wb.x, vb.x, acc1); acc1 = fmaf(wb.y, vb.y, acc1);
        acc1 = fmaf(wb.z, vb.z, acc1); acc1 = fmaf(wb.w, vb.w, acc1);
    }
    float acc = acc0 + acc1;
    #pragma unroll
    for (int o = 16; o; o >>= 1) acc += __shfl_xor_sync(0xffffffffu, acc, o);

    if (lane == 0) {
        if (row < D_INNER) {
            float v  = acc;
            float b1 = conv_buffer[row * 3 + 1];
            float b2 = conv_buffer[row * 3 + 2];
            float4 cw = ((const float4*)conv_w)[row];
            float s = fmaf(b1, cw.x, fmaf(b2, cw.y, fmaf(v, cw.z, fmaf(v, cw.w, conv_b[row]))));
            g_x_conv[row] = s / (1.0f + expf(-s));
        } else {
            float v = acc;
            g_z_silu[row - D_INNER] = v / (1.0f + expf(-v));
        }
    }
}

// ---------------------------------------------------------------------------
// Kernel 2: xp = W_xp @ x_conv  (40 x 8192). Split-K grid (40, 8),
// atomicAdd into g_xp. Also zeroes d_out[0:4096] for k_wout's atomics.
// ---------------------------------------------------------------------------
__global__ __launch_bounds__(256) void k_xp(const float* __restrict__ W_xp,
                                            float* __restrict__ d_out)
{
    __shared__ float red[8];
    const int row   = blockIdx.x;
    const int kbase = blockIdx.y * KT_XP;
    const int tid   = threadIdx.x;

    const int bflat = blockIdx.y * XP_DIM + blockIdx.x;
    if (bflat < D_MODEL / 256) d_out[bflat * 256 + tid] = 0.0f;

    const float4* w4 = (const float4*)(W_xp + (size_t)row * D_INNER + kbase);
    const float4* v4 = (const float4*)(g_x_conv + kbase);

    float acc = 0.0f;
    #pragma unroll
    for (int i = tid; i < KT_XP / 4; i += 256) {
        float4 w = __ldcs(&w4[i]);
        float4 v = v4[i];
        acc = fmaf(w.x, v.x, acc);
        acc = fmaf(w.y, v.y, acc);
        acc = fmaf(w.z, v.z, acc);
        acc = fmaf(w.w, v.w, acc);
    }
    #pragma unroll
    for (int o = 16; o; o >>= 1) acc += __shfl_xor_sync(0xffffffffu, acc, o);
    const int warp = tid >> 5, lane = tid & 31;
    if (lane == 0) red[warp] = acc;
    __syncthreads();
    if (warp == 0) {
        float a = (lane < 8) ? red[lane] : 0.0f;
        #pragma unroll
        for (int o = 4; o; o >>= 1) a += __shfl_xor_sync(0xffffffffu, a, o);
        if (lane == 0) atomicAdd(&g_xp[row], a);
    }
}

// ---------------------------------------------------------------------------
// Kernel 3: per-channel SSM update. Writes new_h into d_out[4096:], y -> g_y.
// ---------------------------------------------------------------------------
__global__ __launch_bounds__(256) void k_ssm(
    const float* __restrict__ W_dt,
    const float* __restrict__ b_dt,
    const float* __restrict__ ssm_state,
    const float* __restrict__ A_log,
    const float* __restrict__ D_param,
    float* __restrict__ d_out)
{
    __shared__ float sxp[XP_DIM];
    const int tid = threadIdx.x;
    if (tid < XP_DIM) sxp[tid] = g_xp[tid];
    __syncthreads();

    const int ch = blockIdx.x * 256 + tid;

    float dtr = b_dt[ch];
    const float4* wd4 = (const float4*)(W_dt + (size_t)ch * DT_RANK);
    float4 w0 = wd4[0], w1 = wd4[1];
    dtr = fmaf(w0.x, sxp[0], dtr);
    dtr = fmaf(w0.y, sxp[1], dtr);
    dtr = fmaf(w0.z, sxp[2], dtr);
    dtr = fmaf(w0.w, sxp[3], dtr);
    dtr = fmaf(w1.x, sxp[4], dtr);
    dtr = fmaf(w1.y, sxp[5], dtr);
    dtr = fmaf(w1.z, sxp[6], dtr);
    dtr = fmaf(w1.w, sxp[7], dtr);
    float dt = (dtr > 20.0f) ? dtr : log1pf(expf(dtr));

    const float xc = g_x_conv[ch];
    const float* al = A_log + (size_t)ch * D_STATE;
    const float* st = ssm_state + (size_t)ch * D_STATE;
    float* hout = d_out + D_MODEL + (size_t)ch * D_STATE;

    float acc = 0.0f;
    #pragma unroll
    for (int s = 0; s < D_STATE; s++) {
        float A    = -expf(al[s]);
        float abar = expf(dt * A);
        float h    = fmaf(abar, st[s], dt * sxp[DT_RANK + s] * xc);
        hout[s] = h;
        acc = fmaf(h, sxp[DT_RANK + D_STATE + s], acc);
    }
    g_y[ch] = fmaf(D_param[ch], xc, acc) * g_z_silu[ch];
}

// ---------------------------------------------------------------------------
// Kernel 4: out = W_out @ y (4096 x 8192). Warp per (row, K-quarter):
// each warp streams a contiguous 8KB quarter-row. grid = 4096 x 128thr
// (1.73 waves, full fill — same geometry as k_win).
// atomicAdd per quarter (out zeroed by k_xp).
// ---------------------------------------------------------------------------
__global__ __launch_bounds__(128, 16) void k_wout(
    const float* __restrict__ W_out,
    float* __restrict__ out)
{
    const int tid  = threadIdx.x;
    const int lane = tid & 31;
    const int g    = blockIdx.x * 4 + (tid >> 5);   // global warp id
    const int row  = g >> 2;
    const int kb4  = (g & 3) * (D_INNER / 16);      // quarter offset in float4s (512)

    const float4* w4 = (const float4*)(W_out + (size_t)row * D_INNER) + kb4;
    const float4* y4 = (const float4*)g_y + kb4;

    float acc0 = 0.0f, acc1 = 0.0f;
    #pragma unroll
    for (int i = lane; i < D_INNER / 16; i += 64) {
        float4 wa = __ldcs(&w4[i]);
        float4 wb = __ldcs(&w4[i + 32]);
        float4 va = y4[i];
        float4 vb = y4[i + 32];
        acc0 = fmaf(wa.x, va.x, acc0); acc0 = fmaf(wa.y, va.y, acc0);
        acc0 = fmaf(wa.z, va.z, acc0); acc0 = fmaf(wa.w, va.w, acc0);
        acc1 = fmaf(wb.x, vb.x, acc1); acc1 = fmaf(wb.y, vb.y, acc1);
        acc1 = fmaf(wb.z, vb.z, acc1); acc1 = fmaf(wb.w, vb.w, acc1);
    }
    float acc = acc0 + acc1;
    #pragma unroll
    for (int o = 16; o; o >>= 1) acc += __shfl_xor_sync(0xffffffffu, acc, o);
    if (lane == 0) atomicAdd(&out[row], acc);
}

// ---------------------------------------------------------------------------
extern "C" void kernel_launch(void* const* d_in, const int* in_sizes, int n_in,
                              void* d_out, int out_size)
{
    const float* x           = (const float*)d_in[0];
    const float* ssm_state   = (const float*)d_in[1];
    const float* conv_buffer = (const float*)d_in[2];
    const float* W_in        = (const float*)d_in[3];
    const float* conv_w      = (const float*)d_in[4];
    const float* conv_b      = (const float*)d_in[5];
    const float* W_xp        = (const float*)d_in[6];
    const float* W_dt        = (const float*)d_in[7];
    const float* b_dt        = (const float*)d_in[8];
    const float* A_log       = (const float*)d_in[9];
    const float* D_param     = (const float*)d_in[10];
    const float* W_out       = (const float*)d_in[11];
    float* out = (float*)d_out;

    k_win <<<(2 * D_INNER) / 4, 128>>>(W_in, x, conv_buffer, conv_w, conv_b);
    k_xp  <<<dim3(XP_DIM, D_INNER / KT_XP), 256>>>(W_xp, out);
    k_ssm <<<D_INNER / 256, 256>>>(W_dt, b_dt, ssm_state, A_log, D_param, out);
    k_wout<<<4 * D_MODEL / 4, 128>>>(W_out, out);
}